// round 7
// baseline (speedup 1.0000x reference)
#include <cuda_runtime.h>
#include <cuda_fp16.h>
#include <math.h>

// Problem: B=4, T=2048, C=512, H=8, d=64 -> 8192 tokens
#define NTOK 8192
#define SEQ  2048

// Scratch — __device__ globals (no cudaMalloc allowed).
__device__ __half  g_lnh[NTOK * 512];        // LN output, fp16
__device__ __half  g_kqvh[NTOK * 1536];      // per token: [k(512)|q(512)|v(512)] fp16
__device__ __half  g_aggh[NTOK * 512];       // attention output, fp16
__device__ __half  g_hh[NTOK * 1024];        // GELU(fc) output, fp16
__device__ __half  g_wkqvh[1536 * 512];
__device__ __half  g_wprojh[512 * 512];
__device__ __half  g_wfch[1024 * 512];
__device__ __half  g_wcprojh[512 * 1024];

// ---------------------------------------------------------------------------
// Fast exp on FMA/ALU pipes (avoids MUFU wall). Rel err ~1e-6.
// ---------------------------------------------------------------------------
__device__ __forceinline__ float fexp(float x) {
    float y = fmaxf(x * 1.4426950408889634f, -80.f);   // log2(e), clamp
    float t = y + 12582912.f;                          // round-to-nearest via RN
    int   i = __float_as_int(t);                       // low bits hold round(y)
    float n = t - 12582912.f;
    float f = y - n;
    float p = 1.3333558146428443e-3f;
    p = fmaf(p, f, 9.6181291076284771e-3f);
    p = fmaf(p, f, 5.5504108664821580e-2f);
    p = fmaf(p, f, 2.4022650695910071e-1f);
    p = fmaf(p, f, 6.9314718055994531e-1f);
    p = fmaf(p, f, 1.0f);
    return __int_as_float(__float_as_int(p) + (i << 23));  // p * 2^n
}

// ---------------------------------------------------------------------------
// fp32 -> fp16 conversion (weights)
// ---------------------------------------------------------------------------
__global__ void __launch_bounds__(256) f2h_kernel(const float* __restrict__ s,
                                                  __half* __restrict__ d, int n) {
    int i = (blockIdx.x * 256 + threadIdx.x) * 4;
    if (i < n) {
        float4 v = *(const float4*)&s[i];
        *(__half2*)&d[i]     = __floats2half2_rn(v.x, v.y);
        *(__half2*)&d[i + 2] = __floats2half2_rn(v.z, v.w);
    }
}

// ---------------------------------------------------------------------------
// LayerNorm (no affine), C=512, warp per row, exact two-pass. fp32 in, fp16 out.
// ---------------------------------------------------------------------------
__global__ void __launch_bounds__(256) ln_kernel(const float* __restrict__ in,
                                                 __half* __restrict__ out) {
    int gw = (blockIdx.x * blockDim.x + threadIdx.x) >> 5;
    int lane = threadIdx.x & 31;
    const float* r = in + (size_t)gw * 512;
    float v[16];
    float s = 0.f;
#pragma unroll
    for (int i = 0; i < 4; i++) {
        float4 t = *(const float4*)(r + i * 128 + lane * 4);
        v[i * 4 + 0] = t.x; v[i * 4 + 1] = t.y; v[i * 4 + 2] = t.z; v[i * 4 + 3] = t.w;
        s += t.x + t.y + t.z + t.w;
    }
#pragma unroll
    for (int o = 16; o > 0; o >>= 1) s += __shfl_xor_sync(0xffffffffu, s, o);
    float mu = s * (1.f / 512.f);
    float q = 0.f;
#pragma unroll
    for (int i = 0; i < 16; i++) { float d = v[i] - mu; q += d * d; }
#pragma unroll
    for (int o = 16; o > 0; o >>= 1) q += __shfl_xor_sync(0xffffffffu, q, o);
    float inv = rsqrtf(q * (1.f / 512.f) + 1e-5f);
    __half* w = out + (size_t)gw * 512;
#pragma unroll
    for (int i = 0; i < 4; i++) {
        *(__half2*)(w + i * 128 + lane * 4) =
            __floats2half2_rn((v[i * 4 + 0] - mu) * inv, (v[i * 4 + 1] - mu) * inv);
        *(__half2*)(w + i * 128 + lane * 4 + 2) =
            __floats2half2_rn((v[i * 4 + 2] - mu) * inv, (v[i * 4 + 3] - mu) * inv);
    }
}

// ---------------------------------------------------------------------------
// HMMA 16x8x16 fp16->fp32
// ---------------------------------------------------------------------------
__device__ __forceinline__ void mma16816(float* c, const unsigned* a, const unsigned* b) {
    asm volatile(
        "mma.sync.aligned.m16n8k16.row.col.f32.f16.f16.f32 "
        "{%0,%1,%2,%3}, {%4,%5,%6,%7}, {%8,%9}, {%0,%1,%2,%3};"
        : "+f"(c[0]), "+f"(c[1]), "+f"(c[2]), "+f"(c[3])
        : "r"(a[0]), "r"(a[1]), "r"(a[2]), "r"(a[3]), "r"(b[0]), "r"(b[1]));
}

// ---------------------------------------------------------------------------
// Tensor-core GEMM: Y[M,N] = Xh[M,K] @ Wh[N,K]^T (+bias)(+gelu)(+residual)
// BM=BN=128, BK=32, 256 threads = 8 warps (2m x 4n), warp tile 64x32.
// Double-buffered smem: one __syncthreads per K-iteration; STS of tile i+1
// overlaps MMAs on tile i. EPI bits: 1=bias, 2=gelu, 4=residual. OUTH: fp16 out.
// ---------------------------------------------------------------------------
#define AS 40   // smem row stride in halfs

template <int EPI, bool OUTH>
__global__ void __launch_bounds__(256, 2) gemm16(const __half* __restrict__ X,
                                                 const __half* __restrict__ W,
                                                 const float* __restrict__ Bv,
                                                 const float* __restrict__ R,
                                                 void* __restrict__ Yp,
                                                 int M, int N, int K) {
    __shared__ __half Xs[2][128 * AS];
    __shared__ __half Ws[2][128 * AS];
    const int n0 = blockIdx.x * 128, m0 = blockIdx.y * 128;
    const int tid = threadIdx.x;
    const int wid = tid >> 5, lane = tid & 31;
    const int wm = wid >> 2, wn = wid & 3;
    const int g = lane >> 2, t = lane & 3;
    const int lrow = tid >> 2, lcol = (tid & 3) * 8;
    const int r0g = lrow, r1g = lrow + 64;

    float acc[4][4][4] = {};
    uint4 xa[2], wb[2];

    // prologue: load tile 0, stage into buffer 0
    xa[0] = *(const uint4*)&X[(size_t)(m0 + r0g) * K + lcol];
    xa[1] = *(const uint4*)&X[(size_t)(m0 + r1g) * K + lcol];
    wb[0] = *(const uint4*)&W[(size_t)(n0 + r0g) * K + lcol];
    wb[1] = *(const uint4*)&W[(size_t)(n0 + r1g) * K + lcol];
    *(uint4*)&Xs[0][r0g * AS + lcol] = xa[0];
    *(uint4*)&Xs[0][r1g * AS + lcol] = xa[1];
    *(uint4*)&Ws[0][r0g * AS + lcol] = wb[0];
    *(uint4*)&Ws[0][r1g * AS + lcol] = wb[1];
    __syncthreads();

    int buf = 0;
    for (int k0 = 0; k0 < K; k0 += 32) {
        const bool more = (k0 + 32 < K);
        // prefetch next tile into registers (latency overlapped with MMAs)
        if (more) {
            xa[0] = *(const uint4*)&X[(size_t)(m0 + r0g) * K + k0 + 32 + lcol];
            xa[1] = *(const uint4*)&X[(size_t)(m0 + r1g) * K + k0 + 32 + lcol];
            wb[0] = *(const uint4*)&W[(size_t)(n0 + r0g) * K + k0 + 32 + lcol];
            wb[1] = *(const uint4*)&W[(size_t)(n0 + r1g) * K + k0 + 32 + lcol];
        }
#pragma unroll
        for (int ks = 0; ks < 32; ks += 16) {
            unsigned af[4][4], bf[4][2];
#pragma unroll
            for (int sm = 0; sm < 4; sm++) {
                int r = wm * 64 + sm * 16 + g;
                af[sm][0] = *(const unsigned*)&Xs[buf][r * AS + ks + t * 2];
                af[sm][1] = *(const unsigned*)&Xs[buf][(r + 8) * AS + ks + t * 2];
                af[sm][2] = *(const unsigned*)&Xs[buf][r * AS + ks + 8 + t * 2];
                af[sm][3] = *(const unsigned*)&Xs[buf][(r + 8) * AS + ks + 8 + t * 2];
            }
#pragma unroll
            for (int sn = 0; sn < 4; sn++) {
                int c = wn * 32 + sn * 8 + g;
                bf[sn][0] = *(const unsigned*)&Ws[buf][c * AS + ks + t * 2];
                bf[sn][1] = *(const unsigned*)&Ws[buf][c * AS + ks + 8 + t * 2];
            }
#pragma unroll
            for (int sm = 0; sm < 4; sm++)
#pragma unroll
                for (int sn = 0; sn < 4; sn++) mma16816(acc[sm][sn], af[sm], bf[sn]);
        }
        if (more) {
            // stage next tile into the other buffer (its readers retired at the
            // previous barrier), then one barrier publishes it + retires `buf`.
            *(uint4*)&Xs[buf ^ 1][r0g * AS + lcol] = xa[0];
            *(uint4*)&Xs[buf ^ 1][r1g * AS + lcol] = xa[1];
            *(uint4*)&Ws[buf ^ 1][r0g * AS + lcol] = wb[0];
            *(uint4*)&Ws[buf ^ 1][r1g * AS + lcol] = wb[1];
            __syncthreads();
            buf ^= 1;
        }
    }

    float* Yf = (float*)Yp;
    __half* Yh = (__half*)Yp;
#pragma unroll
    for (int sm = 0; sm < 4; sm++) {
        int row = m0 + wm * 64 + sm * 16 + g;
#pragma unroll
        for (int sn = 0; sn < 4; sn++) {
            int col = n0 + wn * 32 + sn * 8 + t * 2;
            float2 bias = make_float2(0.f, 0.f);
            if (EPI & 1) bias = *(const float2*)&Bv[col];
#pragma unroll
            for (int hh = 0; hh < 2; hh++) {
                int rr = row + hh * 8;
                float u0 = acc[sm][sn][hh * 2 + 0] + bias.x;
                float u1 = acc[sm][sn][hh * 2 + 1] + bias.y;
                if (EPI & 2) {
                    u0 = 0.5f * u0 * (1.f + erff(u0 * 0.70710678118654752f));
                    u1 = 0.5f * u1 * (1.f + erff(u1 * 0.70710678118654752f));
                }
                if (EPI & 4) {
                    float2 rv = *(const float2*)&R[(size_t)rr * N + col];
                    u0 += rv.x; u1 += rv.y;
                }
                if (OUTH)
                    *(__half2*)&Yh[(size_t)rr * N + col] = __floats2half2_rn(u0, u1);
                else
                    *(float2*)&Yf[(size_t)rr * N + col] = make_float2(u0, u1);
            }
        }
    }
}

// ---------------------------------------------------------------------------
// Flash attention, fp16 MMA, fp32 accum. Br=Bc=128, d=64.
// 8 warps; warp owns 16 q-rows. P stays in registers (C-frag == A-frag trick).
// smem: Qs[128][72], Ks[128][72], Vt[64][136] halfs = 54272 B dynamic.
// grid = (T/128, B*H).
// ---------------------------------------------------------------------------
#define QKS 72
#define VTS 136

__global__ void __launch_bounds__(256) attn_kernel(const __half* __restrict__ kqv,
                                                   __half* __restrict__ agg) {
    extern __shared__ __half smh[];
    __half* Qs = smh;                    // [128][72]
    __half* Ks = Qs + 128 * QKS;         // [128][72]
    __half* Vt = Ks + 128 * QKS;         // [64][136] d-major, seq contiguous

    const int q0 = blockIdx.x * 128;
    const int bh = blockIdx.y;
    const int b = bh >> 3, h = bh & 7;
    const size_t base = (size_t)b * SEQ * 1536 + h * 64;

    const int tid = threadIdx.x;
    const int wid = tid >> 5, lane = tid & 31;
    const int g = lane >> 2, t = lane & 3;
    const int rw = wid * 16;             // warp's q-row base

    // ---- load Q tile into smem (q section at +512) ----
#pragma unroll
    for (int i = 0; i < 4; i++) {
        int idx = tid + i * 256;
        int row = idx >> 3, c8 = (idx & 7) * 8;
        *(uint4*)&Qs[row * QKS + c8] =
            *(const uint4*)&kqv[base + (size_t)(q0 + row) * 1536 + 512 + c8];
    }
    __syncthreads();

    // ---- preload Q fragments (4 d-chunks) ----
    unsigned qf[4][4];
#pragma unroll
    for (int kd = 0; kd < 4; kd++) {
        int r = rw + g;
        qf[kd][0] = *(const unsigned*)&Qs[r * QKS + kd * 16 + t * 2];
        qf[kd][1] = *(const unsigned*)&Qs[(r + 8) * QKS + kd * 16 + t * 2];
        qf[kd][2] = *(const unsigned*)&Qs[r * QKS + kd * 16 + 8 + t * 2];
        qf[kd][3] = *(const unsigned*)&Qs[(r + 8) * QKS + kd * 16 + 8 + t * 2];
    }

    float m0 = -1e30f, m1 = -1e30f, l0 = 0.f, l1 = 0.f;
    float o[8][4] = {};

    for (int j = 0; j < SEQ; j += 128) {
        __syncthreads();   // protect Ks/Vt from previous iteration readers
        // ---- load K tile ----
#pragma unroll
        for (int i = 0; i < 4; i++) {
            int idx = tid + i * 256;
            int row = idx >> 3, c8 = (idx & 7) * 8;
            *(uint4*)&Ks[row * QKS + c8] =
                *(const uint4*)&kqv[base + (size_t)(j + row) * 1536 + c8];
        }
        // ---- load V tile transposed: Vt[d][seq] ----
#pragma unroll
        for (int i = 0; i < 2; i++) {
            int idx = tid + i * 256;
            int sp = idx & 63, dc = idx >> 6;         // seq pair, d-chunk(8)
            uint4 va = *(const uint4*)&kqv[base + (size_t)(j + sp * 2) * 1536 + 1024 + dc * 8];
            uint4 vb = *(const uint4*)&kqv[base + (size_t)(j + sp * 2 + 1) * 1536 + 1024 + dc * 8];
            const __half* ha = (const __half*)&va;
            const __half* hb = (const __half*)&vb;
#pragma unroll
            for (int e = 0; e < 8; e++)
                *(__half2*)&Vt[(dc * 8 + e) * VTS + sp * 2] = __halves2half2(ha[e], hb[e]);
        }
        __syncthreads();

        // ---- S = Q @ K^T : 16 n-tiles x 4 d-chunks ----
        float s[16][4] = {};
#pragma unroll
        for (int jn = 0; jn < 16; jn++) {
            int c = jn * 8 + g;
#pragma unroll
            for (int kd = 0; kd < 4; kd++) {
                unsigned bf[2];
                bf[0] = *(const unsigned*)&Ks[c * QKS + kd * 16 + t * 2];
                bf[1] = *(const unsigned*)&Ks[c * QKS + kd * 16 + 8 + t * 2];
                mma16816(s[jn], qf[kd], bf);
            }
        }

        // ---- online softmax on fragments (rows g and g+8; lane quad shares row) ----
        float mx0 = -1e30f, mx1 = -1e30f;
#pragma unroll
        for (int jn = 0; jn < 16; jn++) {
            s[jn][0] *= 0.125f; s[jn][1] *= 0.125f; s[jn][2] *= 0.125f; s[jn][3] *= 0.125f;
            mx0 = fmaxf(mx0, fmaxf(s[jn][0], s[jn][1]));
            mx1 = fmaxf(mx1, fmaxf(s[jn][2], s[jn][3]));
        }
#pragma unroll
        for (int ofs = 1; ofs <= 2; ofs <<= 1) {
            mx0 = fmaxf(mx0, __shfl_xor_sync(0xffffffffu, mx0, ofs));
            mx1 = fmaxf(mx1, __shfl_xor_sync(0xffffffffu, mx1, ofs));
        }
        float mn0 = fmaxf(m0, mx0), mn1 = fmaxf(m1, mx1);
        float al0 = fexp(m0 - mn0), al1 = fexp(m1 - mn1);
        m0 = mn0; m1 = mn1;
        float ps0 = 0.f, ps1 = 0.f;
#pragma unroll
        for (int jn = 0; jn < 16; jn++) {
            s[jn][0] = fexp(s[jn][0] - mn0);
            s[jn][1] = fexp(s[jn][1] - mn0);
            s[jn][2] = fexp(s[jn][2] - mn1);
            s[jn][3] = fexp(s[jn][3] - mn1);
            ps0 += s[jn][0] + s[jn][1];
            ps1 += s[jn][2] + s[jn][3];
        }
#pragma unroll
        for (int ofs = 1; ofs <= 2; ofs <<= 1) {
            ps0 += __shfl_xor_sync(0xffffffffu, ps0, ofs);
            ps1 += __shfl_xor_sync(0xffffffffu, ps1, ofs);
        }
        l0 = l0 * al0 + ps0;
        l1 = l1 * al1 + ps1;
#pragma unroll
        for (int jd = 0; jd < 8; jd++) {
            o[jd][0] *= al0; o[jd][1] *= al0;
            o[jd][2] *= al1; o[jd][3] *= al1;
        }

        // ---- P C-frag -> A-frag (registers only):
        //      tile 2kc -> a0/a1, tile 2kc+1 -> a2/a3 ----
        unsigned pf[8][4];
#pragma unroll
        for (int kc = 0; kc < 8; kc++) {
            __half2 h0 = __floats2half2_rn(s[2 * kc][0], s[2 * kc][1]);
            __half2 h1 = __floats2half2_rn(s[2 * kc][2], s[2 * kc][3]);
            __half2 h2 = __floats2half2_rn(s[2 * kc + 1][0], s[2 * kc + 1][1]);
            __half2 h3 = __floats2half2_rn(s[2 * kc + 1][2], s[2 * kc + 1][3]);
            pf[kc][0] = *(unsigned*)&h0;
            pf[kc][1] = *(unsigned*)&h1;
            pf[kc][2] = *(unsigned*)&h2;
            pf[kc][3] = *(unsigned*)&h3;
        }

        // ---- O += P @ V : 8 kv-chunks x 8 d-tiles ----
#pragma unroll
        for (int kc = 0; kc < 8; kc++) {
#pragma unroll
            for (int jd = 0; jd < 8; jd++) {
                unsigned bv[2];
                bv[0] = *(const unsigned*)&Vt[(jd * 8 + g) * VTS + kc * 16 + t * 2];
                bv[1] = *(const unsigned*)&Vt[(jd * 8 + g) * VTS + kc * 16 + 8 + t * 2];
                mma16816(o[jd], pf[kc], bv);
            }
        }
    }

    // ---- normalize + store (fp16) ----
    float inv0 = 1.f / l0, inv1 = 1.f / l1;
    size_t r0 = (size_t)(b * SEQ + q0 + rw + g) * 512 + h * 64;
    size_t r1 = (size_t)(b * SEQ + q0 + rw + g + 8) * 512 + h * 64;
#pragma unroll
    for (int jd = 0; jd < 8; jd++) {
        *(__half2*)&agg[r0 + jd * 8 + t * 2] = __floats2half2_rn(o[jd][0] * inv0, o[jd][1] * inv0);
        *(__half2*)&agg[r1 + jd * 8 + t * 2] = __floats2half2_rn(o[jd][2] * inv1, o[jd][3] * inv1);
    }
}

// ---------------------------------------------------------------------------
// Launch
// ---------------------------------------------------------------------------
extern "C" void kernel_launch(void* const* d_in, const int* in_sizes, int n_in,
                              void* d_out, int out_size) {
    const float* x       = (const float*)d_in[0];
    const float* w_kqv   = (const float*)d_in[1];
    const float* b_kqv   = (const float*)d_in[2];
    const float* w_proj  = (const float*)d_in[3];
    const float* b_proj  = (const float*)d_in[4];
    const float* w_fc    = (const float*)d_in[5];
    const float* b_fc    = (const float*)d_in[6];
    const float* w_cproj = (const float*)d_in[7];
    float* out = (float*)d_out;

    __half *lnh, *kqvh, *aggh, *hh, *wkqvh, *wprojh, *wfch, *wcprojh;
    cudaGetSymbolAddress((void**)&lnh,     g_lnh);
    cudaGetSymbolAddress((void**)&kqvh,    g_kqvh);
    cudaGetSymbolAddress((void**)&aggh,    g_aggh);
    cudaGetSymbolAddress((void**)&hh,      g_hh);
    cudaGetSymbolAddress((void**)&wkqvh,   g_wkqvh);
    cudaGetSymbolAddress((void**)&wprojh,  g_wprojh);
    cudaGetSymbolAddress((void**)&wfch,    g_wfch);
    cudaGetSymbolAddress((void**)&wcprojh, g_wcprojh);

    const int smemA = (128 * QKS + 128 * QKS + 64 * VTS) * 2;   // 54272 B
    cudaFuncSetAttribute(attn_kernel, cudaFuncAttributeMaxDynamicSharedMemorySize, smemA);

    // Convert weights to fp16
    f2h_kernel<<<1536 * 512 / 1024, 256>>>(w_kqv,   wkqvh,   1536 * 512);
    f2h_kernel<<<512 * 512 / 1024,  256>>>(w_proj,  wprojh,  512 * 512);
    f2h_kernel<<<1024 * 512 / 1024, 256>>>(w_fc,    wfch,    1024 * 512);
    f2h_kernel<<<512 * 1024 / 1024, 256>>>(w_cproj, wcprojh, 512 * 1024);

    // x1 = x + proj(attn(LN(x)))
    ln_kernel<<<NTOK / 8, 256>>>(x, lnh);
    gemm16<1, true><<<dim3(1536 / 128, NTOK / 128), 256>>>(lnh, wkqvh, b_kqv, nullptr,
                                                           kqvh, NTOK, 1536, 512);
    attn_kernel<<<dim3(SEQ / 128, 32), 256, smemA>>>(kqvh, aggh);
    gemm16<5, false><<<dim3(512 / 128, NTOK / 128), 256>>>(aggh, wprojh, b_proj, x,
                                                           out, NTOK, 512, 512);
    // x2 = x1 + cproj(gelu(fc(LN(x1))))
    ln_kernel<<<NTOK / 8, 256>>>(out, lnh);
    gemm16<3, true><<<dim3(1024 / 128, NTOK / 128), 256>>>(lnh, wfch, b_fc, nullptr,
                                                           hh, NTOK, 1024, 512);
    gemm16<4, false><<<dim3(512 / 128, NTOK / 128), 256>>>(hh, wcprojh, nullptr, out,
                                                           out, NTOK, 512, 1024);
}

// round 9
// speedup vs baseline: 1.0991x; 1.0991x over previous
#include <cuda_runtime.h>
#include <cuda_fp16.h>
#include <math.h>

// Problem: B=4, T=2048, C=512, H=8, d=64 -> 8192 tokens
#define NTOK 8192
#define SEQ  2048

// Scratch — __device__ globals (no cudaMalloc allowed).
__device__ __half  g_lnh[NTOK * 512];        // LN output, fp16
__device__ __half  g_kqvh[NTOK * 1536];      // per token: [k(512)|q(512)|v(512)] fp16
__device__ __half  g_aggh[NTOK * 512];       // attention output, fp16
__device__ __half  g_hh[NTOK * 1024];        // GELU(fc) output, fp16
__device__ __half  g_wkqvh[1536 * 512];
__device__ __half  g_wprojh[512 * 512];
__device__ __half  g_wfch[1024 * 512];
__device__ __half  g_wcprojh[512 * 1024];

// ---------------------------------------------------------------------------
// Fast exp on FMA/ALU pipes (avoids MUFU wall). Rel err ~1e-6.
// ---------------------------------------------------------------------------
__device__ __forceinline__ float fexp(float x) {
    float y = fmaxf(x * 1.4426950408889634f, -80.f);   // log2(e), clamp
    float t = y + 12582912.f;                          // round-to-nearest via RN
    int   i = __float_as_int(t);                       // low bits hold round(y)
    float n = t - 12582912.f;
    float f = y - n;
    float p = 1.3333558146428443e-3f;
    p = fmaf(p, f, 9.6181291076284771e-3f);
    p = fmaf(p, f, 5.5504108664821580e-2f);
    p = fmaf(p, f, 2.4022650695910071e-1f);
    p = fmaf(p, f, 6.9314718055994531e-1f);
    p = fmaf(p, f, 1.0f);
    return __int_as_float(__float_as_int(p) + (i << 23));  // p * 2^n
}

// ---------------------------------------------------------------------------
// ldmatrix x4 (8x8 b16 matrices; lane l supplies row address)
// ---------------------------------------------------------------------------
__device__ __forceinline__ void ldsm4(unsigned& r0, unsigned& r1, unsigned& r2,
                                      unsigned& r3, unsigned saddr) {
    asm volatile("ldmatrix.sync.aligned.m8n8.x4.shared.b16 {%0,%1,%2,%3}, [%4];"
                 : "=r"(r0), "=r"(r1), "=r"(r2), "=r"(r3) : "r"(saddr));
}

// ---------------------------------------------------------------------------
// Fused fp32 -> fp16 conversion of all four weight matrices (one launch).
// Segments (floats): kqv 786432 | proj 262144 | fc 524288 | cproj 524288.
// ---------------------------------------------------------------------------
__global__ void __launch_bounds__(256) f2h_all(const float* __restrict__ w0,
                                               const float* __restrict__ w1,
                                               const float* __restrict__ w2,
                                               const float* __restrict__ w3,
                                               __half* __restrict__ d0,
                                               __half* __restrict__ d1,
                                               __half* __restrict__ d2,
                                               __half* __restrict__ d3) {
    int i = (blockIdx.x * 256 + threadIdx.x) * 4;
    const float* s; __half* d; int off;
    if (i < 786432)       { s = w0; d = d0; off = i; }
    else if (i < 1048576) { s = w1; d = d1; off = i - 786432; }
    else if (i < 1572864) { s = w2; d = d2; off = i - 1048576; }
    else                  { s = w3; d = d3; off = i - 1572864; }
    float4 v = *(const float4*)&s[off];
    *(__half2*)&d[off]     = __floats2half2_rn(v.x, v.y);
    *(__half2*)&d[off + 2] = __floats2half2_rn(v.z, v.w);
}

// ---------------------------------------------------------------------------
// LayerNorm (no affine), C=512, warp per row, exact two-pass. fp32 in, fp16 out.
// ---------------------------------------------------------------------------
__global__ void __launch_bounds__(256) ln_kernel(const float* __restrict__ in,
                                                 __half* __restrict__ out) {
    int gw = (blockIdx.x * blockDim.x + threadIdx.x) >> 5;
    int lane = threadIdx.x & 31;
    const float* r = in + (size_t)gw * 512;
    float v[16];
    float s = 0.f;
#pragma unroll
    for (int i = 0; i < 4; i++) {
        float4 t = *(const float4*)(r + i * 128 + lane * 4);
        v[i * 4 + 0] = t.x; v[i * 4 + 1] = t.y; v[i * 4 + 2] = t.z; v[i * 4 + 3] = t.w;
        s += t.x + t.y + t.z + t.w;
    }
#pragma unroll
    for (int o = 16; o > 0; o >>= 1) s += __shfl_xor_sync(0xffffffffu, s, o);
    float mu = s * (1.f / 512.f);
    float q = 0.f;
#pragma unroll
    for (int i = 0; i < 16; i++) { float d = v[i] - mu; q += d * d; }
#pragma unroll
    for (int o = 16; o > 0; o >>= 1) q += __shfl_xor_sync(0xffffffffu, q, o);
    float inv = rsqrtf(q * (1.f / 512.f) + 1e-5f);
    __half* w = out + (size_t)gw * 512;
#pragma unroll
    for (int i = 0; i < 4; i++) {
        *(__half2*)(w + i * 128 + lane * 4) =
            __floats2half2_rn((v[i * 4 + 0] - mu) * inv, (v[i * 4 + 1] - mu) * inv);
        *(__half2*)(w + i * 128 + lane * 4 + 2) =
            __floats2half2_rn((v[i * 4 + 2] - mu) * inv, (v[i * 4 + 3] - mu) * inv);
    }
}

// ---------------------------------------------------------------------------
// HMMA 16x8x16 fp16->fp32
// ---------------------------------------------------------------------------
__device__ __forceinline__ void mma16816(float* c, const unsigned* a, const unsigned* b) {
    asm volatile(
        "mma.sync.aligned.m16n8k16.row.col.f32.f16.f16.f32 "
        "{%0,%1,%2,%3}, {%4,%5,%6,%7}, {%8,%9}, {%0,%1,%2,%3};"
        : "+f"(c[0]), "+f"(c[1]), "+f"(c[2]), "+f"(c[3])
        : "r"(a[0]), "r"(a[1]), "r"(a[2]), "r"(a[3]), "r"(b[0]), "r"(b[1]));
}

// ---------------------------------------------------------------------------
// Tensor-core GEMM: Y[M,N] = Xh[M,K] @ Wh[N,K]^T (+bias)(+gelu)(+residual)
// BM=BN=128, BK=32, 256 threads = 8 warps (2m x 4n), warp tile 64x32.
// Double-buffered smem, one barrier/K-iter; fragments via ldmatrix.x4.
// EPI bits: 1=bias, 2=gelu, 4=residual. OUTH: fp16 out.
// ---------------------------------------------------------------------------
#define AS 40   // smem row stride in halfs (rows tile all 32 banks for LDSM)

template <int EPI, bool OUTH>
__global__ void __launch_bounds__(256, 2) gemm16(const __half* __restrict__ X,
                                                 const __half* __restrict__ W,
                                                 const float* __restrict__ Bv,
                                                 const float* __restrict__ R,
                                                 void* __restrict__ Yp,
                                                 int M, int N, int K) {
    __shared__ __half Xs[2][128 * AS];
    __shared__ __half Ws[2][128 * AS];
    const int n0 = blockIdx.x * 128, m0 = blockIdx.y * 128;
    const int tid = threadIdx.x;
    const int wid = tid >> 5, lane = tid & 31;
    const int wm = wid >> 2, wn = wid & 3;
    const int g = lane >> 2, t = lane & 3;
    const int lrow = tid >> 2, lcol = (tid & 3) * 8;
    const int r0g = lrow, r1g = lrow + 64;

    // per-lane ldmatrix row-address components (validated mapping):
    // A: m0=rows@ks, m1=rows+8@ks, m2=rows@ks+8, m3=rows+8@ks+8
    // B: m0=c@ks, m1=c@ks+8, m2=c+8@ks, m3=c+8@ks+8   (two sn tiles per x4)
    const int lr8 = lane & 7, lb3 = (lane >> 3) & 1, lb4 = (lane >> 4) & 1;
    const int aoff = (wm * 64 + lr8 + lb3 * 8) * AS + lb4 * 8;
    const int boff = (wn * 32 + lr8 + lb4 * 8) * AS + lb3 * 8;
    const unsigned xsb[2] = {(unsigned)__cvta_generic_to_shared(&Xs[0][0]),
                             (unsigned)__cvta_generic_to_shared(&Xs[1][0])};
    const unsigned wsb[2] = {(unsigned)__cvta_generic_to_shared(&Ws[0][0]),
                             (unsigned)__cvta_generic_to_shared(&Ws[1][0])};

    float acc[4][4][4] = {};
    uint4 xa[2], wb[2];

    // prologue: load tile 0, stage into buffer 0
    xa[0] = *(const uint4*)&X[(size_t)(m0 + r0g) * K + lcol];
    xa[1] = *(const uint4*)&X[(size_t)(m0 + r1g) * K + lcol];
    wb[0] = *(const uint4*)&W[(size_t)(n0 + r0g) * K + lcol];
    wb[1] = *(const uint4*)&W[(size_t)(n0 + r1g) * K + lcol];
    *(uint4*)&Xs[0][r0g * AS + lcol] = xa[0];
    *(uint4*)&Xs[0][r1g * AS + lcol] = xa[1];
    *(uint4*)&Ws[0][r0g * AS + lcol] = wb[0];
    *(uint4*)&Ws[0][r1g * AS + lcol] = wb[1];
    __syncthreads();

    int buf = 0;
    for (int k0 = 0; k0 < K; k0 += 32) {
        const bool more = (k0 + 32 < K);
        if (more) {
            xa[0] = *(const uint4*)&X[(size_t)(m0 + r0g) * K + k0 + 32 + lcol];
            xa[1] = *(const uint4*)&X[(size_t)(m0 + r1g) * K + k0 + 32 + lcol];
            wb[0] = *(const uint4*)&W[(size_t)(n0 + r0g) * K + k0 + 32 + lcol];
            wb[1] = *(const uint4*)&W[(size_t)(n0 + r1g) * K + k0 + 32 + lcol];
        }
#pragma unroll
        for (int ks = 0; ks < 32; ks += 16) {
            unsigned af[4][4], bf[4][2];
#pragma unroll
            for (int sm = 0; sm < 4; sm++)
                ldsm4(af[sm][0], af[sm][1], af[sm][2], af[sm][3],
                      xsb[buf] + 2u * (aoff + sm * 16 * AS + ks));
            ldsm4(bf[0][0], bf[0][1], bf[1][0], bf[1][1],
                  wsb[buf] + 2u * (boff + ks));
            ldsm4(bf[2][0], bf[2][1], bf[3][0], bf[3][1],
                  wsb[buf] + 2u * (boff + 16 * AS + ks));
#pragma unroll
            for (int sm = 0; sm < 4; sm++)
#pragma unroll
                for (int sn = 0; sn < 4; sn++) mma16816(acc[sm][sn], af[sm], bf[sn]);
        }
        if (more) {
            *(uint4*)&Xs[buf ^ 1][r0g * AS + lcol] = xa[0];
            *(uint4*)&Xs[buf ^ 1][r1g * AS + lcol] = xa[1];
            *(uint4*)&Ws[buf ^ 1][r0g * AS + lcol] = wb[0];
            *(uint4*)&Ws[buf ^ 1][r1g * AS + lcol] = wb[1];
            __syncthreads();
            buf ^= 1;
        }
    }

    float* Yf = (float*)Yp;
    __half* Yh = (__half*)Yp;
#pragma unroll
    for (int sm = 0; sm < 4; sm++) {
        int row = m0 + wm * 64 + sm * 16 + g;
#pragma unroll
        for (int sn = 0; sn < 4; sn++) {
            int col = n0 + wn * 32 + sn * 8 + t * 2;
            float2 bias = make_float2(0.f, 0.f);
            if (EPI & 1) bias = *(const float2*)&Bv[col];
#pragma unroll
            for (int hh = 0; hh < 2; hh++) {
                int rr = row + hh * 8;
                float u0 = acc[sm][sn][hh * 2 + 0] + bias.x;
                float u1 = acc[sm][sn][hh * 2 + 1] + bias.y;
                if (EPI & 2) {
                    u0 = 0.5f * u0 * (1.f + erff(u0 * 0.70710678118654752f));
                    u1 = 0.5f * u1 * (1.f + erff(u1 * 0.70710678118654752f));
                }
                if (EPI & 4) {
                    float2 rv = *(const float2*)&R[(size_t)rr * N + col];
                    u0 += rv.x; u1 += rv.y;
                }
                if (OUTH)
                    *(__half2*)&Yh[(size_t)rr * N + col] = __floats2half2_rn(u0, u1);
                else
                    *(float2*)&Yf[(size_t)rr * N + col] = make_float2(u0, u1);
            }
        }
    }
}

// ---------------------------------------------------------------------------
// Flash attention, fp16 MMA, fp32 accum. Br=Bc=128, d=64.
// 8 warps; warp owns 16 q-rows. P stays in registers (C-frag == A-frag trick).
// 1/sqrt(d) folded into Q fragments. K/V fragments via ldmatrix.x4.
// K/V global loads for iteration j+1 register-prefetched during compute of j.
// smem: Qs[128][72], Ks[128][72], Vt[64][136] halfs = 54272 B dynamic.
// grid = (T/128, B*H).
// ---------------------------------------------------------------------------
#define QKS 72
#define VTS 136

__global__ void __launch_bounds__(256) attn_kernel(const __half* __restrict__ kqv,
                                                   __half* __restrict__ agg) {
    extern __shared__ __half smh[];
    __half* Qs = smh;                    // [128][72]
    __half* Ks = Qs + 128 * QKS;         // [128][72]
    __half* Vt = Ks + 128 * QKS;         // [64][136] d-major, seq contiguous

    const int q0 = blockIdx.x * 128;
    const int bh = blockIdx.y;
    const int b = bh >> 3, h = bh & 7;
    const size_t base = (size_t)b * SEQ * 1536 + h * 64;

    const int tid = threadIdx.x;
    const int wid = tid >> 5, lane = tid & 31;
    const int g = lane >> 2, t = lane & 3;
    const int rw = wid * 16;             // warp's q-row base
    const int lr8 = lane & 7, lb3 = (lane >> 3) & 1, lb4 = (lane >> 4) & 1;

    const unsigned qsb = (unsigned)__cvta_generic_to_shared(Qs);
    const unsigned ksb = (unsigned)__cvta_generic_to_shared(Ks);
    const unsigned vtb = (unsigned)__cvta_generic_to_shared(Vt);
    // A-style (Q): m0=rows@k, m1=rows+8@k, m2=rows@k+8, m3=rows+8@k+8
    const int qoff = (rw + lr8 + lb3 * 8) * QKS + lb4 * 8;
    // B-style pairs (K/V): m0=c@k, m1=c@k+8, m2=c+8@k, m3=c+8@k+8
    const int koff = (lr8 + lb4 * 8) * QKS + lb3 * 8;
    const int voff = (lr8 + lb4 * 8) * VTS + lb3 * 8;

    // per-thread K/V load coordinates
    const int krow = tid >> 3, kc8 = (tid & 7) * 8;     // K: rows tid>>3 (+32*i)
    const int vsp = tid & 63, vdc = tid >> 6;           // V: seq pair, d-chunk

    // ---- load Q tile into smem (q section at +512) ----
#pragma unroll
    for (int i = 0; i < 4; i++) {
        int idx = tid + i * 256;
        int row = idx >> 3, c8 = (idx & 7) * 8;
        *(uint4*)&Qs[row * QKS + c8] =
            *(const uint4*)&kqv[base + (size_t)(q0 + row) * 1536 + 512 + c8];
    }
    __syncthreads();

    // ---- preload Q fragments (4 d-chunks), fold in 1/sqrt(d)=0.125 (exact) ----
    const __half2 qscale = __float2half2_rn(0.125f);
    unsigned qf[4][4];
#pragma unroll
    for (int kd = 0; kd < 4; kd++) {
        ldsm4(qf[kd][0], qf[kd][1], qf[kd][2], qf[kd][3],
              qsb + 2u * (qoff + kd * 16));
#pragma unroll
        for (int i = 0; i < 4; i++) {
            __half2 v = __hmul2(*reinterpret_cast<__half2*>(&qf[kd][i]), qscale);
            qf[kd][i] = *reinterpret_cast<unsigned*>(&v);
        }
    }

    float m0 = -1e30f, m1 = -1e30f, l0 = 0.f, l1 = 0.f;
    float o[8][4] = {};

    // ---- prefetch K/V tile for j=0 into registers ----
    uint4 kr[4], vra[2], vrb[2];
#pragma unroll
    for (int i = 0; i < 4; i++)
        kr[i] = *(const uint4*)&kqv[base + (size_t)(krow + 32 * i) * 1536 + kc8];
#pragma unroll
    for (int i = 0; i < 2; i++) {
        int dc = vdc + 4 * i;
        vra[i] = *(const uint4*)&kqv[base + (size_t)(vsp * 2) * 1536 + 1024 + dc * 8];
        vrb[i] = *(const uint4*)&kqv[base + (size_t)(vsp * 2 + 1) * 1536 + 1024 + dc * 8];
    }

    for (int j = 0; j < SEQ; j += 128) {
        __syncthreads();   // previous iteration's readers done with Ks/Vt
        // ---- stage prefetched K tile ----
#pragma unroll
        for (int i = 0; i < 4; i++)
            *(uint4*)&Ks[(krow + 32 * i) * QKS + kc8] = kr[i];
        // ---- stage prefetched V tile transposed: Vt[d][seq] ----
#pragma unroll
        for (int i = 0; i < 2; i++) {
            int dc = vdc + 4 * i;
            const __half* ha = (const __half*)&vra[i];
            const __half* hb = (const __half*)&vrb[i];
#pragma unroll
            for (int e = 0; e < 8; e++)
                *(__half2*)&Vt[(dc * 8 + e) * VTS + vsp * 2] = __halves2half2(ha[e], hb[e]);
        }
        __syncthreads();

        // ---- prefetch next iteration's K/V while computing ----
        if (j + 128 < SEQ) {
            size_t nb = base + (size_t)(j + 128) * 1536;
#pragma unroll
            for (int i = 0; i < 4; i++)
                kr[i] = *(const uint4*)&kqv[nb + (size_t)(krow + 32 * i) * 1536 + kc8];
#pragma unroll
            for (int i = 0; i < 2; i++) {
                int dc = vdc + 4 * i;
                vra[i] = *(const uint4*)&kqv[nb + (size_t)(vsp * 2) * 1536 + 1024 + dc * 8];
                vrb[i] = *(const uint4*)&kqv[nb + (size_t)(vsp * 2 + 1) * 1536 + 1024 + dc * 8];
            }
        }

        // ---- S = Q*0.125 @ K^T : 8 jn-pairs x 4 d-chunks (K frags via LDSM) ----
        float s[16][4] = {};
#pragma unroll
        for (int jnp = 0; jnp < 8; jnp++) {
#pragma unroll
            for (int kd = 0; kd < 4; kd++) {
                unsigned u0, u1, u2, u3;
                ldsm4(u0, u1, u2, u3,
                      ksb + 2u * (koff + jnp * 16 * QKS + kd * 16));
                unsigned p0[2] = {u0, u1}, p1[2] = {u2, u3};
                mma16816(s[2 * jnp], qf[kd], p0);
                mma16816(s[2 * jnp + 1], qf[kd], p1);
            }
        }

        // ---- online softmax on fragments (rows g and g+8; lane quad shares row) ----
        float mx0 = -1e30f, mx1 = -1e30f;
#pragma unroll
        for (int jn = 0; jn < 16; jn++) {
            mx0 = fmaxf(mx0, fmaxf(s[jn][0], s[jn][1]));
            mx1 = fmaxf(mx1, fmaxf(s[jn][2], s[jn][3]));
        }
#pragma unroll
        for (int ofs = 1; ofs <= 2; ofs <<= 1) {
            mx0 = fmaxf(mx0, __shfl_xor_sync(0xffffffffu, mx0, ofs));
            mx1 = fmaxf(mx1, __shfl_xor_sync(0xffffffffu, mx1, ofs));
        }
        float mn0 = fmaxf(m0, mx0), mn1 = fmaxf(m1, mx1);
        float al0 = fexp(m0 - mn0), al1 = fexp(m1 - mn1);
        m0 = mn0; m1 = mn1;
        float ps0 = 0.f, ps1 = 0.f;
#pragma unroll
        for (int jn = 0; jn < 16; jn++) {
            s[jn][0] = fexp(s[jn][0] - mn0);
            s[jn][1] = fexp(s[jn][1] - mn0);
            s[jn][2] = fexp(s[jn][2] - mn1);
            s[jn][3] = fexp(s[jn][3] - mn1);
            ps0 += s[jn][0] + s[jn][1];
            ps1 += s[jn][2] + s[jn][3];
        }
#pragma unroll
        for (int ofs = 1; ofs <= 2; ofs <<= 1) {
            ps0 += __shfl_xor_sync(0xffffffffu, ps0, ofs);
            ps1 += __shfl_xor_sync(0xffffffffu, ps1, ofs);
        }
        l0 = l0 * al0 + ps0;
        l1 = l1 * al1 + ps1;
#pragma unroll
        for (int jd = 0; jd < 8; jd++) {
            o[jd][0] *= al0; o[jd][1] *= al0;
            o[jd][2] *= al1; o[jd][3] *= al1;
        }

        // ---- P C-frag -> A-frag (registers only):
        //      tile 2kc -> a0/a1, tile 2kc+1 -> a2/a3 ----
        unsigned pf[8][4];
#pragma unroll
        for (int kc = 0; kc < 8; kc++) {
            __half2 h0 = __floats2half2_rn(s[2 * kc][0], s[2 * kc][1]);
            __half2 h1 = __floats2half2_rn(s[2 * kc][2], s[2 * kc][3]);
            __half2 h2 = __floats2half2_rn(s[2 * kc + 1][0], s[2 * kc + 1][1]);
            __half2 h3 = __floats2half2_rn(s[2 * kc + 1][2], s[2 * kc + 1][3]);
            pf[kc][0] = *(unsigned*)&h0;
            pf[kc][1] = *(unsigned*)&h1;
            pf[kc][2] = *(unsigned*)&h2;
            pf[kc][3] = *(unsigned*)&h3;
        }

        // ---- O += P @ V : 8 kv-chunks x 4 jd-pairs (V frags via LDSM) ----
#pragma unroll
        for (int kc = 0; kc < 8; kc++) {
#pragma unroll
            for (int jdp = 0; jdp < 4; jdp++) {
                unsigned u0, u1, u2, u3;
                ldsm4(u0, u1, u2, u3,
                      vtb + 2u * (voff + jdp * 16 * VTS + kc * 16));
                unsigned p0[2] = {u0, u1}, p1[2] = {u2, u3};
                mma16816(o[2 * jdp], pf[kc], p0);
                mma16816(o[2 * jdp + 1], pf[kc], p1);
            }
        }
    }

    // ---- normalize + store (fp16) ----
    float inv0 = 1.f / l0, inv1 = 1.f / l1;
    size_t r0 = (size_t)(b * SEQ + q0 + rw + g) * 512 + h * 64;
    size_t r1 = (size_t)(b * SEQ + q0 + rw + g + 8) * 512 + h * 64;
#pragma unroll
    for (int jd = 0; jd < 8; jd++) {
        *(__half2*)&agg[r0 + jd * 8 + t * 2] = __floats2half2_rn(o[jd][0] * inv0, o[jd][1] * inv0);
        *(__half2*)&agg[r1 + jd * 8 + t * 2] = __floats2half2_rn(o[jd][2] * inv1, o[jd][3] * inv1);
    }
}

// ---------------------------------------------------------------------------
// Launch
// ---------------------------------------------------------------------------
extern "C" void kernel_launch(void* const* d_in, const int* in_sizes, int n_in,
                              void* d_out, int out_size) {
    const float* x       = (const float*)d_in[0];
    const float* w_kqv   = (const float*)d_in[1];
    const float* b_kqv   = (const float*)d_in[2];
    const float* w_proj  = (const float*)d_in[3];
    const float* b_proj  = (const float*)d_in[4];
    const float* w_fc    = (const float*)d_in[5];
    const float* b_fc    = (const float*)d_in[6];
    const float* w_cproj = (const float*)d_in[7];
    float* out = (float*)d_out;

    __half *lnh, *kqvh, *aggh, *hh, *wkqvh, *wprojh, *wfch, *wcprojh;
    cudaGetSymbolAddress((void**)&lnh,     g_lnh);
    cudaGetSymbolAddress((void**)&kqvh,    g_kqvh);
    cudaGetSymbolAddress((void**)&aggh,    g_aggh);
    cudaGetSymbolAddress((void**)&hh,      g_hh);
    cudaGetSymbolAddress((void**)&wkqvh,   g_wkqvh);
    cudaGetSymbolAddress((void**)&wprojh,  g_wprojh);
    cudaGetSymbolAddress((void**)&wfch,    g_wfch);
    cudaGetSymbolAddress((void**)&wcprojh, g_wcprojh);

    const int smemA = (128 * QKS + 128 * QKS + 64 * VTS) * 2;   // 54272 B
    cudaFuncSetAttribute(attn_kernel, cudaFuncAttributeMaxDynamicSharedMemorySize, smemA);

    // Convert all weights to fp16 in one launch (2097152 floats / 4 per thread)
    f2h_all<<<2048, 256>>>(w_kqv, w_proj, w_fc, w_cproj, wkqvh, wprojh, wfch, wcprojh);

    // x1 = x + proj(attn(LN(x)))
    ln_kernel<<<NTOK / 8, 256>>>(x, lnh);
    gemm16<1, true><<<dim3(1536 / 128, NTOK / 128), 256>>>(lnh, wkqvh, b_kqv, nullptr,
                                                           kqvh, NTOK, 1536, 512);
    attn_kernel<<<dim3(SEQ / 128, 32), 256, smemA>>>(kqvh, aggh);
    gemm16<5, false><<<dim3(512 / 128, NTOK / 128), 256>>>(aggh, wprojh, b_proj, x,
                                                           out, NTOK, 512, 512);
    // x2 = x1 + cproj(gelu(fc(LN(x1))))
    ln_kernel<<<NTOK / 8, 256>>>(out, lnh);
    gemm16<3, true><<<dim3(1024 / 128, NTOK / 128), 256>>>(lnh, wfch, b_fc, nullptr,
                                                           hh, NTOK, 1024, 512);
    gemm16<4, false><<<dim3(512 / 128, NTOK / 128), 256>>>(hh, wcprojh, nullptr, out,
                                                           out, NTOK, 512, 1024);
}